// round 9
// baseline (speedup 1.0000x reference)
#include <cuda_runtime.h>
#include <cuda_fp16.h>
#include <math.h>

#define Bn 1024
#define Ln 64
#define Hn 512
#define NCTA 256
#define NTHREADS 256

// fp16 ping-pong state + fp16 weights (converted once/launch), fp16 history.
__device__ __half g_S16[2][4][Bn][Hn];   // 8 MB
__device__ __half g_W16[7][Hn][Hn];      // [0..3]=Wc, [4..6]=Win_rest, [k][n] layout
__device__ __half g_h16[Ln][Bn][Hn];     // 64 MB layer-3 outputs
__device__ float  g_lp[8][Bn];           // per-t-chunk partial log-probs
__device__ unsigned g_count;
__device__ volatile unsigned g_gen;

// Dynamic smem: A[4][128][40] halfs + B[4][32][72] halfs
#define A_STAGE_HALFS (128 * 40)
#define B_STAGE_HALFS (32 * 72)
#define A_HALFS (4 * A_STAGE_HALFS)
#define SMEM_BYTES ((A_HALFS + 4 * B_STAGE_HALFS) * 2)   // 59392 B

// ---------------------------------------------------------------------------
__device__ __forceinline__ void cp16(void* dst, const void* src) {
    unsigned d = (unsigned)__cvta_generic_to_shared(dst);
    asm volatile("cp.async.cg.shared.global [%0], [%1], 16;" :: "r"(d), "l"(src));
}
__device__ __forceinline__ void cp_commit() {
    asm volatile("cp.async.commit_group;" ::: "memory");
}
template <int N>
__device__ __forceinline__ void cp_wait() {
    asm volatile("cp.async.wait_group %0;" :: "n"(N) : "memory");
}
__device__ __forceinline__ void ldsm4(unsigned r[4], const void* p) {
    unsigned a = (unsigned)__cvta_generic_to_shared(p);
    asm volatile("ldmatrix.sync.aligned.m8n8.x4.shared.b16 {%0,%1,%2,%3}, [%4];"
                 : "=r"(r[0]), "=r"(r[1]), "=r"(r[2]), "=r"(r[3]) : "r"(a));
}
__device__ __forceinline__ void ldsm4t(unsigned r[4], const void* p) {
    unsigned a = (unsigned)__cvta_generic_to_shared(p);
    asm volatile("ldmatrix.sync.aligned.m8n8.x4.trans.shared.b16 {%0,%1,%2,%3}, [%4];"
                 : "=r"(r[0]), "=r"(r[1]), "=r"(r[2]), "=r"(r[3]) : "r"(a));
}
__device__ __forceinline__ void mma_f16(float c[4], const unsigned a[4],
                                        unsigned b0, unsigned b1) {
    asm volatile(
        "mma.sync.aligned.m16n8k16.row.col.f32.f16.f16.f32 "
        "{%0,%1,%2,%3}, {%4,%5,%6,%7}, {%8,%9}, {%0,%1,%2,%3};"
        : "+f"(c[0]), "+f"(c[1]), "+f"(c[2]), "+f"(c[3])
        : "r"(a[0]), "r"(a[1]), "r"(a[2]), "r"(a[3]), "r"(b0), "r"(b1));
}

// Global barrier: 256 CTAs, 2/SM via launch_bounds, all co-resident in wave 1.
__device__ __forceinline__ void gbar(unsigned target) {
    __syncthreads();
    if (threadIdx.x == 0) {
        __threadfence();
        unsigned t = atomicAdd(&g_count, 1);
        if (t == NCTA - 1) {
            atomicExch(&g_count, 0);
            __threadfence();
            g_gen = target;
        } else {
            while ((int)(g_gen - target) < 0) {}
            __threadfence();
        }
    }
    __syncthreads();
}

// Stage one BK=32 chunk into ring stage s (A: 128x32, B: 32x64). 3 cp16/thread.
template <bool DUAL>
__device__ __forceinline__ void stage_chunk(
    __half* Asm, __half* Bsm, int s, int cc,
    const __half* A1, const __half* A2,
    const __half* W1, const __half* W2,
    int m0, int n0, int tid)
{
    const bool ph = DUAL && (cc >= 16);
    const __half* As = ph ? A2 : A1;
    const __half* Ws = ph ? W2 : W1;
    const int kc = (cc & 15) * 32;

    const int ar  = tid >> 1;              // 0..127
    const int asg = (tid & 1) * 16;        // halfs 0 or 16
    __half* ad = Asm + s * A_STAGE_HALFS + ar * 40 + asg;
    const __half* asrc = As + (m0 + ar) * Hn + kc + asg;
    cp16(ad,     asrc);
    cp16(ad + 8, asrc + 8);

    const int br = tid >> 3;               // 0..31
    const int bs = (tid & 7) * 8;          // halfs 0..56
    cp16(Bsm + s * B_STAGE_HALFS + br * 72 + bs, Ws + (kc + br) * Hn + n0 + bs);
}

// One 128x64 job: C = elu(A1@W1 [+ A2@W2] + bias [+ Win0 one-hot row]).
// 4-deep cp.async ring; warps: mw = warp>>1 (4 x 32 rows), nw = warp&1 (2 x 32 cols).
template <bool DUAL, bool LAYER0, bool STORE>
__device__ __forceinline__ void do_job(
    __half* Asm, __half* Bsm, int t,
    const __half* A1, const __half* A2,
    const __half* W1, const __half* W2,
    const float* bias, const int* x, const float* Win0,
    __half* Cout, int m0, int n0)
{
    const int tid  = threadIdx.x;
    const int warp = tid >> 5, lane = tid & 31;
    const int mw = warp >> 1;
    const int nw = warp & 1;
    const int quad = lane >> 2, qt = lane & 3;
    const int lrow = lane & 15, lhi = (lane >> 4) << 3;

    float acc[2][4][4];
#pragma unroll
    for (int a = 0; a < 2; a++)
#pragma unroll
        for (int b = 0; b < 4; b++)
#pragma unroll
            for (int v = 0; v < 4; v++) acc[a][b][v] = 0.f;

    const int NCH = DUAL ? 32 : 16;

    // prologue: fill 3 of 4 ring stages
#pragma unroll
    for (int p = 0; p < 3; p++) {
        stage_chunk<DUAL>(Asm, Bsm, p, p, A1, A2, W1, W2, m0, n0, tid);
        cp_commit();
    }

    for (int cc = 0; cc < NCH; cc++) {
        // exact-count wait: chunks cc..min(cc+2,NCH-1) are in flight
        if (cc < NCH - 2)      cp_wait<2>();
        else if (cc == NCH - 2) cp_wait<1>();
        else                    cp_wait<0>();
        __syncthreads();

        if (cc + 3 < NCH) {
            stage_chunk<DUAL>(Asm, Bsm, (cc + 3) & 3, cc + 3, A1, A2, W1, W2, m0, n0, tid);
            cp_commit();
        }

        const __half* Ab = Asm + (cc & 3) * A_STAGE_HALFS;
        const __half* Bb = Bsm + (cc & 3) * B_STAGE_HALFS;
#pragma unroll
        for (int k16 = 0; k16 < 32; k16 += 16) {
            unsigned a[2][4];
            ldsm4(a[0], Ab + (mw * 32 + lrow) * 40 + k16 + lhi);
            ldsm4(a[1], Ab + (mw * 32 + 16 + lrow) * 40 + k16 + lhi);
            unsigned b0[4], b1[4];
            ldsm4t(b0, Bb + (k16 + lrow) * 72 + nw * 32 + lhi);
            ldsm4t(b1, Bb + (k16 + lrow) * 72 + nw * 32 + 16 + lhi);
#pragma unroll
            for (int ma = 0; ma < 2; ma++) {
                mma_f16(acc[ma][0], a[ma], b0[0], b0[1]);
                mma_f16(acc[ma][1], a[ma], b0[2], b0[3]);
                mma_f16(acc[ma][2], a[ma], b1[0], b1[1]);
                mma_f16(acc[ma][3], a[ma], b1[2], b1[3]);
            }
        }
    }

    // epilogue: + bias (+ Win0[x[t-1]] row for layer 0), ELU, store
#pragma unroll
    for (int ma = 0; ma < 2; ma++) {
        const int r0 = m0 + mw * 32 + ma * 16 + quad;
        const int r1 = r0 + 8;
        int idx0 = 0, idx1 = 0;
        const bool l0add = LAYER0 && (t > 0);
        if (l0add) {
            idx0 = x[r0 * Ln + (t - 1)];
            idx1 = x[r1 * Ln + (t - 1)];
        }
#pragma unroll
        for (int nb = 0; nb < 4; nb++) {
            const int col = n0 + nw * 32 + nb * 8 + 2 * qt;
            const float2 bv = *reinterpret_cast<const float2*>(&bias[col]);
            float2 w0 = make_float2(0.f, 0.f), w1 = make_float2(0.f, 0.f);
            if (l0add) {
                w0 = *reinterpret_cast<const float2*>(&Win0[idx0 * Hn + col]);
                w1 = *reinterpret_cast<const float2*>(&Win0[idx1 * Hn + col]);
            }
            float v0 = acc[ma][nb][0] + bv.x + w0.x;
            float v1 = acc[ma][nb][1] + bv.y + w0.y;
            float v2 = acc[ma][nb][2] + bv.x + w1.x;
            float v3 = acc[ma][nb][3] + bv.y + w1.y;
            v0 = (v0 > 0.f) ? v0 : expm1f(v0);
            v1 = (v1 > 0.f) ? v1 : expm1f(v1);
            v2 = (v2 > 0.f) ? v2 : expm1f(v2);
            v3 = (v3 > 0.f) ? v3 : expm1f(v3);
            const __half2 p01 = __floats2half2_rn(v0, v1);
            const __half2 p23 = __floats2half2_rn(v2, v3);
            *reinterpret_cast<__half2*>(&Cout[r0 * Hn + col]) = p01;
            *reinterpret_cast<__half2*>(&Cout[r1 * Hn + col]) = p23;
            if (STORE) {
                *reinterpret_cast<__half2*>(&g_h16[t][r0][col]) = p01;
                *reinterpret_cast<__half2*>(&g_h16[t][r1][col]) = p23;
            }
        }
    }
}

// ---------------------------------------------------------------------------
__global__ void __launch_bounds__(NTHREADS, 2) rnn_persistent(
    const int*   __restrict__ x,         // [B][L]
    const float* __restrict__ Win0,      // [2][H]
    const float* __restrict__ Win_rest,  // [3][H][H]
    const float* __restrict__ Wc,        // [4][H][H]
    const float* __restrict__ bc)        // [4][H]
{
    extern __shared__ __align__(16) __half dsm[];
    __half* Asm = dsm;
    __half* Bsm = dsm + A_HALFS;

    const int tid  = threadIdx.x;
    const int cta  = blockIdx.x;
    const int gtid = cta * NTHREADS + tid;

    unsigned base = g_gen;               // stable until first barrier releases
    unsigned bar  = 0;

    // --- prologue: convert weights to fp16, zero initial state -------------
    {
        const float4* wc4 = reinterpret_cast<const float4*>(Wc);
        __half2* d = reinterpret_cast<__half2*>(&g_W16[0][0][0]);
        for (int i = gtid; i < 4 * Hn * Hn / 4; i += NCTA * NTHREADS) {
            float4 v = wc4[i];
            d[2 * i]     = __floats2half2_rn(v.x, v.y);
            d[2 * i + 1] = __floats2half2_rn(v.z, v.w);
        }
        const float4* wr4 = reinterpret_cast<const float4*>(Win_rest);
        __half2* d2 = reinterpret_cast<__half2*>(&g_W16[4][0][0]);
        for (int i = gtid; i < 3 * Hn * Hn / 4; i += NCTA * NTHREADS) {
            float4 v = wr4[i];
            d2[2 * i]     = __floats2half2_rn(v.x, v.y);
            d2[2 * i + 1] = __floats2half2_rn(v.z, v.w);
        }
        uint4* z = reinterpret_cast<uint4*>(&g_S16[0][0][0][0]);
        const uint4 z4 = make_uint4(0u, 0u, 0u, 0u);
        for (int i = gtid; i < 4 * Bn * Hn * 2 / 16; i += NCTA * NTHREADS)
            z[i] = z4;
    }
    gbar(base + (++bar));

    // --- wavefront: phase w runs layers j with t = w - j --------------------
    const int slot = cta >> 6;             // 0..3: active-layer slot
    const int tile = cta & 63;             // 64 tiles of 128x64
    const int m0 = (tile >> 3) * 128;      // 8 m-tiles
    const int n0 = (tile & 7) * 64;        // 8 n-tiles

    for (int w = 0; w < Ln + 3; w++) {
        const int jhi = (w < 3) ? w : 3;
        const int jlo = (w > Ln - 1) ? (w - (Ln - 1)) : 0;
        const int nact = jhi - jlo + 1;
        if (slot < nact) {
            const int j = jhi - slot;
            const int t = w - j;
            const int pin = t & 1, pout = pin ^ 1;
            const __half* A1 = &g_S16[pin][j][0][0];
            const __half* A2 = (j > 0) ? &g_S16[pout][j - 1][0][0] : A1;
            const __half* W1 = &g_W16[j][0][0];
            const __half* W2 = (j > 0) ? &g_W16[4 + j - 1][0][0] : W1;
            const float* bias = bc + j * Hn;
            __half* Cout = &g_S16[pout][j][0][0];
            switch (j) {
                case 0:
                    do_job<false, true, false>(Asm, Bsm, t, A1, A2, W1, W2, bias, x, Win0, Cout, m0, n0);
                    break;
                case 3:
                    do_job<true, false, true>(Asm, Bsm, t, A1, A2, W1, W2, bias, x, Win0, Cout, m0, n0);
                    break;
                default:
                    do_job<true, false, false>(Asm, Bsm, t, A1, A2, W1, W2, bias, x, Win0, Cout, m0, n0);
                    break;
            }
        }
        gbar(base + (++bar));
    }
}

// ---------------------------------------------------------------------------
// Log-prob partials: warp (b, tc) handles 8 timesteps, writes g_lp[tc][b].
// ---------------------------------------------------------------------------
__global__ void logp_part(const float* __restrict__ Wout,  // [H][2]
                          const float* __restrict__ bout,  // [2]
                          const int*   __restrict__ xsym)  // [B][L]
{
    const int gw   = (blockIdx.x * blockDim.x + threadIdx.x) >> 5;
    const int lane = threadIdx.x & 31;
    const int b  = gw >> 3;
    const int tc = gw & 7;
    if (b >= Bn) return;

    float w0[16], w1[16];
#pragma unroll
    for (int i = 0; i < 8; i++) {
        const int k = lane * 2 + 64 * i;
        w0[2 * i]     = Wout[k * 2 + 0];
        w1[2 * i]     = Wout[k * 2 + 1];
        w0[2 * i + 1] = Wout[(k + 1) * 2 + 0];
        w1[2 * i + 1] = Wout[(k + 1) * 2 + 1];
    }
    const float b0 = bout[0], b1 = bout[1];

    float acc = 0.f;
#pragma unroll
    for (int tt = 0; tt < 8; tt++) {
        const int t = tc * 8 + tt;
        const __half* h = &g_h16[t][b][0];
        float s0 = 0.f, s1 = 0.f;
#pragma unroll
        for (int i = 0; i < 8; i++) {
            const __half2 hv = *reinterpret_cast<const __half2*>(&h[lane * 2 + 64 * i]);
            const float h0 = __half2float(hv.x);
            const float h1 = __half2float(hv.y);
            s0 += h0 * w0[2 * i] + h1 * w0[2 * i + 1];
            s1 += h0 * w1[2 * i] + h1 * w1[2 * i + 1];
        }
#pragma unroll
        for (int off = 16; off > 0; off >>= 1) {
            s0 += __shfl_xor_sync(0xffffffffu, s0, off);
            s1 += __shfl_xor_sync(0xffffffffu, s1, off);
        }
        s0 += b0; s1 += b1;
        const float m   = fmaxf(s0, s1);
        const float lse = m + logf(expf(s0 - m) + expf(s1 - m));
        const float sel = (xsym[b * Ln + t] == 0) ? s0 : s1;
        acc += sel - lse;
    }
    if (lane == 0) g_lp[tc][b] = acc;
}

// Deterministic final sum: out[b] = 0.5 * sum_tc g_lp[tc][b]
__global__ void logp_sum(float* __restrict__ out) {
    const int b = blockIdx.x * blockDim.x + threadIdx.x;
    if (b >= Bn) return;
    float s = 0.f;
#pragma unroll
    for (int tc = 0; tc < 8; tc++) s += g_lp[tc][b];
    out[b] = 0.5f * s;
}

// ---------------------------------------------------------------------------
extern "C" void kernel_launch(void* const* d_in, const int* in_sizes, int n_in,
                              void* d_out, int out_size) {
    (void)in_sizes; (void)n_in; (void)out_size;
    const int*   x        = (const int*)  d_in[0];  // [B, L]
    const float* Win0     = (const float*)d_in[1];  // [2, H]
    const float* Win_rest = (const float*)d_in[2];  // [3, H, H]
    const float* Wc       = (const float*)d_in[3];  // [4, H, H]
    const float* bc       = (const float*)d_in[4];  // [4, H]
    const float* Wout     = (const float*)d_in[5];  // [H, 2]
    const float* bout     = (const float*)d_in[6];  // [2]
    float* out = (float*)d_out;                     // [B]

    cudaFuncSetAttribute(rnn_persistent,
                         cudaFuncAttributeMaxDynamicSharedMemorySize, SMEM_BYTES);

    rnn_persistent<<<NCTA, NTHREADS, SMEM_BYTES>>>(x, Win0, Win_rest, Wc, bc);
    logp_part<<<(Bn * 8) / 8, 256>>>(Wout, bout, x);   // 1024 blocks, 8 warps each
    logp_sum<<<Bn / 256, 256>>>(out);
}

// round 10
// speedup vs baseline: 1.0451x; 1.0451x over previous
#include <cuda_runtime.h>
#include <cuda_fp16.h>
#include <math.h>

#define Bn 1024
#define Ln 64
#define Hn 512
#define NCTA 128
#define NTHREADS 256

// fp16 ping-pong state + fp16 weights (converted once/launch), fp16 history.
__device__ __half g_S16[2][4][Bn][Hn];   // 8 MB
__device__ __half g_W16[7][Hn][Hn];      // [0..3]=Wc, [4..6]=Win_rest, [k][n] layout
__device__ __half g_h16[Ln][Bn][Hn];     // 64 MB layer-3 outputs
__device__ float  g_lp[8][Bn];           // per-t-chunk partial log-probs
__device__ unsigned g_count;
__device__ volatile unsigned g_gen;

struct Smem {
    __half A[2][128][40];    // 128x32 tile, pitch 80B  (LDSM conflict-free)
    __half B[2][32][136];    // 32x128 tile, pitch 272B (LDSM conflict-free)
};                           // 37.9 KB static

// ---------------------------------------------------------------------------
__device__ __forceinline__ void cp16(void* dst, const void* src) {
    unsigned d = (unsigned)__cvta_generic_to_shared(dst);
    asm volatile("cp.async.cg.shared.global [%0], [%1], 16;" :: "r"(d), "l"(src));
}
__device__ __forceinline__ void cp_commit() {
    asm volatile("cp.async.commit_group;" ::: "memory");
}
__device__ __forceinline__ void cp_wait0() {
    asm volatile("cp.async.wait_group 0;" ::: "memory");
}
__device__ __forceinline__ void ldsm4(unsigned r[4], const void* p) {
    unsigned a = (unsigned)__cvta_generic_to_shared(p);
    asm volatile("ldmatrix.sync.aligned.m8n8.x4.shared.b16 {%0,%1,%2,%3}, [%4];"
                 : "=r"(r[0]), "=r"(r[1]), "=r"(r[2]), "=r"(r[3]) : "r"(a));
}
__device__ __forceinline__ void ldsm4t(unsigned r[4], const void* p) {
    unsigned a = (unsigned)__cvta_generic_to_shared(p);
    asm volatile("ldmatrix.sync.aligned.m8n8.x4.trans.shared.b16 {%0,%1,%2,%3}, [%4];"
                 : "=r"(r[0]), "=r"(r[1]), "=r"(r[2]), "=r"(r[3]) : "r"(a));
}
__device__ __forceinline__ void mma_f16(float c[4], const unsigned a[4],
                                        unsigned b0, unsigned b1) {
    asm volatile(
        "mma.sync.aligned.m16n8k16.row.col.f32.f16.f16.f32 "
        "{%0,%1,%2,%3}, {%4,%5,%6,%7}, {%8,%9}, {%0,%1,%2,%3};"
        : "+f"(c[0]), "+f"(c[1]), "+f"(c[2]), "+f"(c[3])
        : "r"(a[0]), "r"(a[1]), "r"(a[2]), "r"(a[3]), "r"(b0), "r"(b1));
}

// Global barrier: 128 CTAs, 1/SM, all co-resident.
__device__ __forceinline__ void gbar(unsigned target) {
    __syncthreads();
    if (threadIdx.x == 0) {
        __threadfence();
        unsigned t = atomicAdd(&g_count, 1);
        if (t == NCTA - 1) {
            atomicExch(&g_count, 0);
            __threadfence();
            g_gen = target;
        } else {
            while ((int)(g_gen - target) < 0) {}
            __threadfence();
        }
    }
    __syncthreads();
}

// Stage one BK=32 chunk (A: 128x32 = 8KB, B: 32x128 = 8KB). 4 cp16/thread.
template <bool DUAL>
__device__ __forceinline__ void stage_chunk(
    Smem* sm, int st, int cc,
    const __half* A1, const __half* A2,
    const __half* W1, const __half* W2,
    int m0, int n0, int tid)
{
    const bool ph = DUAL && (cc >= 16);
    const __half* As = ph ? A2 : A1;
    const __half* Ws = ph ? W2 : W1;
    const int kc = (cc & 15) * 32;

    const int ar  = tid >> 1;              // 0..127
    const int asg = (tid & 1) * 16;        // halfs 0 or 16
    const __half* asrc = As + (m0 + ar) * Hn + kc + asg;
    cp16(&sm->A[st][ar][asg],     asrc);
    cp16(&sm->A[st][ar][asg + 8], asrc + 8);

    const int br = tid >> 3;               // 0..31
    const int bs = (tid & 7) * 16;         // halfs 0..112
    const __half* bsrc = Ws + (kc + br) * Hn + n0 + bs;
    cp16(&sm->B[st][br][bs],     bsrc);
    cp16(&sm->B[st][br][bs + 8], bsrc + 8);
}

// One 128x128 job: C = elu(A1@W1 [+ A2@W2] + bias [+ Win0 one-hot row]).
// Warp tile 32x64: mw = warp&3 (4 x 32 rows), nw = warp>>2 (2 x 64 cols).
template <bool DUAL, bool LAYER0, bool STORE>
__device__ __forceinline__ void do_job(
    Smem* sm, int t,
    const __half* A1, const __half* A2,
    const __half* W1, const __half* W2,
    const float* bias, const int* x, const float* Win0,
    __half* Cout, int m0, int n0)
{
    const int tid  = threadIdx.x;
    const int warp = tid >> 5, lane = tid & 31;
    const int mw = warp & 3;
    const int nw = warp >> 2;
    const int quad = lane >> 2, qt = lane & 3;
    const int lrow = lane & 15, lhi = (lane >> 4) << 3;

    float acc[2][8][4];
#pragma unroll
    for (int a = 0; a < 2; a++)
#pragma unroll
        for (int b = 0; b < 8; b++)
#pragma unroll
            for (int v = 0; v < 4; v++) acc[a][b][v] = 0.f;

    const int NCH = DUAL ? 32 : 16;
    stage_chunk<DUAL>(sm, 0, 0, A1, A2, W1, W2, m0, n0, tid);
    cp_commit();

    for (int cc = 0; cc < NCH; cc++) {
        cp_wait0();
        __syncthreads();
        const int st = cc & 1;
        if (cc + 1 < NCH)
            stage_chunk<DUAL>(sm, st ^ 1, cc + 1, A1, A2, W1, W2, m0, n0, tid);
        cp_commit();

#pragma unroll
        for (int k16 = 0; k16 < 32; k16 += 16) {
            unsigned a[2][4];
            ldsm4(a[0], &sm->A[st][mw * 32 + lrow][k16 + lhi]);
            ldsm4(a[1], &sm->A[st][mw * 32 + 16 + lrow][k16 + lhi]);
            unsigned b[4][4];
#pragma unroll
            for (int g = 0; g < 4; g++)
                ldsm4t(b[g], &sm->B[st][k16 + lrow][nw * 64 + g * 16 + lhi]);
#pragma unroll
            for (int ma = 0; ma < 2; ma++)
#pragma unroll
                for (int g = 0; g < 4; g++) {
                    mma_f16(acc[ma][2 * g],     a[ma], b[g][0], b[g][1]);
                    mma_f16(acc[ma][2 * g + 1], a[ma], b[g][2], b[g][3]);
                }
        }
    }

    // epilogue: + bias (+ Win0[x[t-1]] row for layer 0), ELU, store
#pragma unroll
    for (int ma = 0; ma < 2; ma++) {
        const int r0 = m0 + mw * 32 + ma * 16 + quad;
        const int r1 = r0 + 8;
        int idx0 = 0, idx1 = 0;
        const bool l0add = LAYER0 && (t > 0);
        if (l0add) {
            idx0 = x[r0 * Ln + (t - 1)];
            idx1 = x[r1 * Ln + (t - 1)];
        }
#pragma unroll
        for (int nb = 0; nb < 8; nb++) {
            const int col = n0 + nw * 64 + nb * 8 + 2 * qt;
            const float2 bv = *reinterpret_cast<const float2*>(&bias[col]);
            float2 w0 = make_float2(0.f, 0.f), w1 = make_float2(0.f, 0.f);
            if (l0add) {
                w0 = *reinterpret_cast<const float2*>(&Win0[idx0 * Hn + col]);
                w1 = *reinterpret_cast<const float2*>(&Win0[idx1 * Hn + col]);
            }
            float v0 = acc[ma][nb][0] + bv.x + w0.x;
            float v1 = acc[ma][nb][1] + bv.y + w0.y;
            float v2 = acc[ma][nb][2] + bv.x + w1.x;
            float v3 = acc[ma][nb][3] + bv.y + w1.y;
            v0 = (v0 > 0.f) ? v0 : expm1f(v0);
            v1 = (v1 > 0.f) ? v1 : expm1f(v1);
            v2 = (v2 > 0.f) ? v2 : expm1f(v2);
            v3 = (v3 > 0.f) ? v3 : expm1f(v3);
            const __half2 p01 = __floats2half2_rn(v0, v1);
            const __half2 p23 = __floats2half2_rn(v2, v3);
            *reinterpret_cast<__half2*>(&Cout[r0 * Hn + col]) = p01;
            *reinterpret_cast<__half2*>(&Cout[r1 * Hn + col]) = p23;
            if (STORE) {
                *reinterpret_cast<__half2*>(&g_h16[t][r0][col]) = p01;
                *reinterpret_cast<__half2*>(&g_h16[t][r1][col]) = p23;
            }
        }
    }
}

// ---------------------------------------------------------------------------
__global__ void __launch_bounds__(NTHREADS) rnn_persistent(
    const int*   __restrict__ x,         // [B][L]
    const float* __restrict__ Win0,      // [2][H]
    const float* __restrict__ Win_rest,  // [3][H][H]
    const float* __restrict__ Wc,        // [4][H][H]
    const float* __restrict__ bc)        // [4][H]
{
    __shared__ __align__(16) Smem sm;

    const int tid  = threadIdx.x;
    const int cta  = blockIdx.x;
    const int gtid = cta * NTHREADS + tid;

    unsigned base = g_gen;               // stable until first barrier releases
    unsigned bar  = 0;

    // --- prologue: convert weights to fp16, zero initial state -------------
    {
        const float4* wc4 = reinterpret_cast<const float4*>(Wc);
        __half2* d = reinterpret_cast<__half2*>(&g_W16[0][0][0]);
        for (int i = gtid; i < 4 * Hn * Hn / 4; i += NCTA * NTHREADS) {
            float4 v = wc4[i];
            d[2 * i]     = __floats2half2_rn(v.x, v.y);
            d[2 * i + 1] = __floats2half2_rn(v.z, v.w);
        }
        const float4* wr4 = reinterpret_cast<const float4*>(Win_rest);
        __half2* d2 = reinterpret_cast<__half2*>(&g_W16[4][0][0]);
        for (int i = gtid; i < 3 * Hn * Hn / 4; i += NCTA * NTHREADS) {
            float4 v = wr4[i];
            d2[2 * i]     = __floats2half2_rn(v.x, v.y);
            d2[2 * i + 1] = __floats2half2_rn(v.z, v.w);
        }
        uint4* z = reinterpret_cast<uint4*>(&g_S16[0][0][0][0]);
        const uint4 z4 = make_uint4(0u, 0u, 0u, 0u);
        for (int i = gtid; i < 4 * Bn * Hn * 2 / 16; i += NCTA * NTHREADS)
            z[i] = z4;
    }
    gbar(base + (++bar));

    // --- wavefront: phase w runs layers j with t = w - j --------------------
    const int slot = cta >> 5;             // 0..3: active-layer slot
    const int tile = cta & 31;             // 32 tiles of 128x128
    const int m0 = (tile >> 2) * 128;      // 8 m-tiles
    const int n0 = (tile & 3) * 128;       // 4 n-tiles

    for (int w = 0; w < Ln + 3; w++) {
        const int jhi = (w < 3) ? w : 3;
        const int jlo = (w > Ln - 1) ? (w - (Ln - 1)) : 0;
        const int nact = jhi - jlo + 1;
        if (slot < nact) {
            const int j = jhi - slot;
            const int t = w - j;
            const int pin = t & 1, pout = pin ^ 1;
            const __half* A1 = &g_S16[pin][j][0][0];
            const __half* A2 = (j > 0) ? &g_S16[pout][j - 1][0][0] : A1;
            const __half* W1 = &g_W16[j][0][0];
            const __half* W2 = (j > 0) ? &g_W16[4 + j - 1][0][0] : W1;
            const float* bias = bc + j * Hn;
            __half* Cout = &g_S16[pout][j][0][0];
            switch (j) {
                case 0:
                    do_job<false, true, false>(&sm, t, A1, A2, W1, W2, bias, x, Win0, Cout, m0, n0);
                    break;
                case 3:
                    do_job<true, false, true>(&sm, t, A1, A2, W1, W2, bias, x, Win0, Cout, m0, n0);
                    break;
                default:
                    do_job<true, false, false>(&sm, t, A1, A2, W1, W2, bias, x, Win0, Cout, m0, n0);
                    break;
            }
        }
        gbar(base + (++bar));
    }
}

// ---------------------------------------------------------------------------
// Log-prob partials: warp (b, tc) handles 8 timesteps, writes g_lp[tc][b].
// ---------------------------------------------------------------------------
__global__ void logp_part(const float* __restrict__ Wout,  // [H][2]
                          const float* __restrict__ bout,  // [2]
                          const int*   __restrict__ xsym)  // [B][L]
{
    const int gw   = (blockIdx.x * blockDim.x + threadIdx.x) >> 5;
    const int lane = threadIdx.x & 31;
    const int b  = gw >> 3;
    const int tc = gw & 7;
    if (b >= Bn) return;

    float w0[16], w1[16];
#pragma unroll
    for (int i = 0; i < 8; i++) {
        const int k = lane * 2 + 64 * i;
        w0[2 * i]     = Wout[k * 2 + 0];
        w1[2 * i]     = Wout[k * 2 + 1];
        w0[2 * i + 1] = Wout[(k + 1) * 2 + 0];
        w1[2 * i + 1] = Wout[(k + 1) * 2 + 1];
    }
    const float b0 = bout[0], b1 = bout[1];

    float acc = 0.f;
#pragma unroll
    for (int tt = 0; tt < 8; tt++) {
        const int t = tc * 8 + tt;
        const __half* h = &g_h16[t][b][0];
        float s0 = 0.f, s1 = 0.f;
#pragma unroll
        for (int i = 0; i < 8; i++) {
            const __half2 hv = *reinterpret_cast<const __half2*>(&h[lane * 2 + 64 * i]);
            const float h0 = __half2float(hv.x);
            const float h1 = __half2float(hv.y);
            s0 += h0 * w0[2 * i] + h1 * w0[2 * i + 1];
            s1 += h0 * w1[2 * i] + h1 * w1[2 * i + 1];
        }
#pragma unroll
        for (int off = 16; off > 0; off >>= 1) {
            s0 += __shfl_xor_sync(0xffffffffu, s0, off);
            s1 += __shfl_xor_sync(0xffffffffu, s1, off);
        }
        s0 += b0; s1 += b1;
        const float m   = fmaxf(s0, s1);
        const float lse = m + logf(expf(s0 - m) + expf(s1 - m));
        const float sel = (xsym[b * Ln + t] == 0) ? s0 : s1;
        acc += sel - lse;
    }
    if (lane == 0) g_lp[tc][b] = acc;
}

// Deterministic final sum: out[b] = 0.5 * sum_tc g_lp[tc][b]
__global__ void logp_sum(float* __restrict__ out) {
    const int b = blockIdx.x * blockDim.x + threadIdx.x;
    if (b >= Bn) return;
    float s = 0.f;
#pragma unroll
    for (int tc = 0; tc < 8; tc++) s += g_lp[tc][b];
    out[b] = 0.5f * s;
}

// ---------------------------------------------------------------------------
extern "C" void kernel_launch(void* const* d_in, const int* in_sizes, int n_in,
                              void* d_out, int out_size) {
    (void)in_sizes; (void)n_in; (void)out_size;
    const int*   x        = (const int*)  d_in[0];  // [B, L]
    const float* Win0     = (const float*)d_in[1];  // [2, H]
    const float* Win_rest = (const float*)d_in[2];  // [3, H, H]
    const float* Wc       = (const float*)d_in[3];  // [4, H, H]
    const float* bc       = (const float*)d_in[4];  // [4, H]
    const float* Wout     = (const float*)d_in[5];  // [H, 2]
    const float* bout     = (const float*)d_in[6];  // [2]
    float* out = (float*)d_out;                     // [B]

    rnn_persistent<<<NCTA, NTHREADS>>>(x, Win0, Win_rest, Wc, bc);
    logp_part<<<(Bn * 8) / 8, 256>>>(Wout, bout, x);   // 1024 blocks, 8 warps each
    logp_sum<<<Bn / 256, 256>>>(out);
}

// round 11
// speedup vs baseline: 1.0687x; 1.0226x over previous
#include <cuda_runtime.h>
#include <cuda_fp16.h>
#include <math.h>

#define Bn 1024
#define Ln 64
#define Hn 512
#define NCTA 256
#define NTHREADS 256

// fp16 ping-pong state + fp16 weights (converted once/launch), fp16 history.
__device__ __half g_S16[2][4][Bn][Hn];   // 8 MB
__device__ __half g_W16[7][Hn][Hn];      // [0..3]=Wc, [4..6]=Win_rest, [k][n] layout
__device__ __half g_h16[Ln][Bn][Hn];     // 64 MB layer-3 outputs
__device__ float  g_lp[8][Bn];           // per-t-chunk partial log-probs
__device__ unsigned g_count;
__device__ volatile unsigned g_gen;

struct Smem {
    __half A[2][128][40];   // 128x32 tile, pitch 80B (LDSM conflict-free)
    __half B[2][32][72];    // 32x64 tile,  pitch 144B (LDSM conflict-free)
};                          // 29696 B static -> 2 CTAs/SM

// ---------------------------------------------------------------------------
__device__ __forceinline__ void cp16(void* dst, const void* src) {
    unsigned d = (unsigned)__cvta_generic_to_shared(dst);
    asm volatile("cp.async.cg.shared.global [%0], [%1], 16;" :: "r"(d), "l"(src));
}
__device__ __forceinline__ void cp_commit() {
    asm volatile("cp.async.commit_group;" ::: "memory");
}
__device__ __forceinline__ void cp_wait0() {
    asm volatile("cp.async.wait_group 0;" ::: "memory");
}
__device__ __forceinline__ void ldsm4(unsigned r[4], const void* p) {
    unsigned a = (unsigned)__cvta_generic_to_shared(p);
    asm volatile("ldmatrix.sync.aligned.m8n8.x4.shared.b16 {%0,%1,%2,%3}, [%4];"
                 : "=r"(r[0]), "=r"(r[1]), "=r"(r[2]), "=r"(r[3]) : "r"(a));
}
__device__ __forceinline__ void ldsm4t(unsigned r[4], const void* p) {
    unsigned a = (unsigned)__cvta_generic_to_shared(p);
    asm volatile("ldmatrix.sync.aligned.m8n8.x4.trans.shared.b16 {%0,%1,%2,%3}, [%4];"
                 : "=r"(r[0]), "=r"(r[1]), "=r"(r[2]), "=r"(r[3]) : "r"(a));
}
// fp16-accumulate MMA: D(f16x2 x2) = A*B + C(f16)
__device__ __forceinline__ void mma_hh(unsigned c[2], const unsigned a[4],
                                       unsigned b0, unsigned b1) {
    asm volatile(
        "mma.sync.aligned.m16n8k16.row.col.f16.f16.f16.f16 "
        "{%0,%1}, {%2,%3,%4,%5}, {%6,%7}, {%0,%1};"
        : "+r"(c[0]), "+r"(c[1])
        : "r"(a[0]), "r"(a[1]), "r"(a[2]), "r"(a[3]), "r"(b0), "r"(b1));
}

// Global barrier: 256 CTAs, 2/SM via launch_bounds, all co-resident in wave 1.
__device__ __forceinline__ void gbar(unsigned target) {
    __syncthreads();
    if (threadIdx.x == 0) {
        __threadfence();
        unsigned t = atomicAdd(&g_count, 1);
        if (t == NCTA - 1) {
            atomicExch(&g_count, 0);
            __threadfence();
            g_gen = target;
        } else {
            while ((int)(g_gen - target) < 0) {}
            __threadfence();
        }
    }
    __syncthreads();
}

// Stage one BK=32 chunk (A: 128x32 = 64B/row, B: 32x64 = 128B/row). 3 cp16/thread.
template <bool DUAL>
__device__ __forceinline__ void stage_chunk(
    Smem* sm, int st, int cc,
    const __half* A1, const __half* A2,
    const __half* W1, const __half* W2,
    int m0, int n0, int tid)
{
    const bool ph = DUAL && (cc >= 16);
    const __half* As = ph ? A2 : A1;
    const __half* Ws = ph ? W2 : W1;
    const int kc = (cc & 15) * 32;

    const int ar  = tid >> 1;              // 0..127
    const int asg = (tid & 1) * 16;        // halfs 0 or 16
    cp16(&sm->A[st][ar][asg],     As + (m0 + ar) * Hn + kc + asg);
    cp16(&sm->A[st][ar][asg + 8], As + (m0 + ar) * Hn + kc + asg + 8);

    const int br = tid >> 3;               // 0..31
    const int bs = (tid & 7) * 8;          // halfs 0..56
    cp16(&sm->B[st][br][bs], Ws + (kc + br) * Hn + n0 + bs);
}

// One 128x64 job: C = elu(A1@W1 [+ A2@W2] + bias [+ Win0 one-hot row]).
// fp16-accum MMA within K=64 (2 chunks), promoted into fp32 accumulators.
template <bool DUAL, bool LAYER0, bool STORE>
__device__ __forceinline__ void do_job(
    Smem* sm, int t,
    const __half* A1, const __half* A2,
    const __half* W1, const __half* W2,
    const float* bias, const int* x, const float* Win0,
    __half* Cout, int m0, int n0)
{
    const int tid  = threadIdx.x;
    const int warp = tid >> 5, lane = tid & 31;
    const int mw = warp >> 1;
    const int nw = warp & 1;
    const int quad = lane >> 2, qt = lane & 3;
    const int lrow = lane & 15, lhi = (lane >> 4) << 3;

    float acc[2][4][4];
#pragma unroll
    for (int a = 0; a < 2; a++)
#pragma unroll
        for (int b = 0; b < 4; b++)
#pragma unroll
            for (int v = 0; v < 4; v++) acc[a][b][v] = 0.f;

    unsigned cacc[2][4][2];                 // fp16 partial accumulators

    const int NCH = DUAL ? 32 : 16;
    stage_chunk<DUAL>(sm, 0, 0, A1, A2, W1, W2, m0, n0, tid);
    cp_commit();

    for (int cc = 0; cc < NCH; cc++) {
        cp_wait0();
        __syncthreads();
        const int st = cc & 1;
        if (cc + 1 < NCH)
            stage_chunk<DUAL>(sm, st ^ 1, cc + 1, A1, A2, W1, W2, m0, n0, tid);
        cp_commit();

        if ((cc & 1) == 0) {                // start a fresh fp16 chain (K=64)
#pragma unroll
            for (int a = 0; a < 2; a++)
#pragma unroll
                for (int b = 0; b < 4; b++) {
                    cacc[a][b][0] = 0u;
                    cacc[a][b][1] = 0u;
                }
        }

#pragma unroll
        for (int k16 = 0; k16 < 32; k16 += 16) {
            unsigned a[2][4];
            ldsm4(a[0], &sm->A[st][mw * 32 + lrow][k16 + lhi]);
            ldsm4(a[1], &sm->A[st][mw * 32 + 16 + lrow][k16 + lhi]);
            unsigned b0[4], b1[4];
            ldsm4t(b0, &sm->B[st][k16 + lrow][nw * 32 + lhi]);
            ldsm4t(b1, &sm->B[st][k16 + lrow][nw * 32 + 16 + lhi]);
#pragma unroll
            for (int ma = 0; ma < 2; ma++) {
                mma_hh(cacc[ma][0], a[ma], b0[0], b0[1]);
                mma_hh(cacc[ma][1], a[ma], b0[2], b0[3]);
                mma_hh(cacc[ma][2], a[ma], b1[0], b1[1]);
                mma_hh(cacc[ma][3], a[ma], b1[2], b1[3]);
            }
        }

        if (cc & 1) {                        // promote fp16 chain into fp32
#pragma unroll
            for (int ma = 0; ma < 2; ma++)
#pragma unroll
                for (int nb = 0; nb < 4; nb++) {
                    const float2 lo =
                        __half22float2(*reinterpret_cast<__half2*>(&cacc[ma][nb][0]));
                    const float2 hi =
                        __half22float2(*reinterpret_cast<__half2*>(&cacc[ma][nb][1]));
                    acc[ma][nb][0] += lo.x;
                    acc[ma][nb][1] += lo.y;
                    acc[ma][nb][2] += hi.x;
                    acc[ma][nb][3] += hi.y;
                }
        }
    }

    // epilogue: + bias (+ Win0[x[t-1]] row for layer 0), ELU, store
#pragma unroll
    for (int ma = 0; ma < 2; ma++) {
        const int r0 = m0 + mw * 32 + ma * 16 + quad;
        const int r1 = r0 + 8;
        int idx0 = 0, idx1 = 0;
        const bool l0add = LAYER0 && (t > 0);
        if (l0add) {
            idx0 = x[r0 * Ln + (t - 1)];
            idx1 = x[r1 * Ln + (t - 1)];
        }
#pragma unroll
        for (int nb = 0; nb < 4; nb++) {
            const int col = n0 + nw * 32 + nb * 8 + 2 * qt;
            const float2 bv = *reinterpret_cast<const float2*>(&bias[col]);
            float2 w0 = make_float2(0.f, 0.f), w1 = make_float2(0.f, 0.f);
            if (l0add) {
                w0 = *reinterpret_cast<const float2*>(&Win0[idx0 * Hn + col]);
                w1 = *reinterpret_cast<const float2*>(&Win0[idx1 * Hn + col]);
            }
            float v0 = acc[ma][nb][0] + bv.x + w0.x;
            float v1 = acc[ma][nb][1] + bv.y + w0.y;
            float v2 = acc[ma][nb][2] + bv.x + w1.x;
            float v3 = acc[ma][nb][3] + bv.y + w1.y;
            v0 = (v0 > 0.f) ? v0 : expm1f(v0);
            v1 = (v1 > 0.f) ? v1 : expm1f(v1);
            v2 = (v2 > 0.f) ? v2 : expm1f(v2);
            v3 = (v3 > 0.f) ? v3 : expm1f(v3);
            const __half2 p01 = __floats2half2_rn(v0, v1);
            const __half2 p23 = __floats2half2_rn(v2, v3);
            *reinterpret_cast<__half2*>(&Cout[r0 * Hn + col]) = p01;
            *reinterpret_cast<__half2*>(&Cout[r1 * Hn + col]) = p23;
            if (STORE) {
                *reinterpret_cast<__half2*>(&g_h16[t][r0][col]) = p01;
                *reinterpret_cast<__half2*>(&g_h16[t][r1][col]) = p23;
            }
        }
    }
}

// ---------------------------------------------------------------------------
__global__ void __launch_bounds__(NTHREADS, 2) rnn_persistent(
    const int*   __restrict__ x,         // [B][L]
    const float* __restrict__ Win0,      // [2][H]
    const float* __restrict__ Win_rest,  // [3][H][H]
    const float* __restrict__ Wc,        // [4][H][H]
    const float* __restrict__ bc)        // [4][H]
{
    __shared__ __align__(16) Smem sm;

    const int tid  = threadIdx.x;
    const int cta  = blockIdx.x;
    const int gtid = cta * NTHREADS + tid;

    unsigned base = g_gen;               // stable until first barrier releases
    unsigned bar  = 0;

    // --- prologue: convert weights to fp16, zero initial state -------------
    {
        const float4* wc4 = reinterpret_cast<const float4*>(Wc);
        __half2* d = reinterpret_cast<__half2*>(&g_W16[0][0][0]);
        for (int i = gtid; i < 4 * Hn * Hn / 4; i += NCTA * NTHREADS) {
            float4 v = wc4[i];
            d[2 * i]     = __floats2half2_rn(v.x, v.y);
            d[2 * i + 1] = __floats2half2_rn(v.z, v.w);
        }
        const float4* wr4 = reinterpret_cast<const float4*>(Win_rest);
        __half2* d2 = reinterpret_cast<__half2*>(&g_W16[4][0][0]);
        for (int i = gtid; i < 3 * Hn * Hn / 4; i += NCTA * NTHREADS) {
            float4 v = wr4[i];
            d2[2 * i]     = __floats2half2_rn(v.x, v.y);
            d2[2 * i + 1] = __floats2half2_rn(v.z, v.w);
        }
        uint4* z = reinterpret_cast<uint4*>(&g_S16[0][0][0][0]);
        const uint4 z4 = make_uint4(0u, 0u, 0u, 0u);
        for (int i = gtid; i < 4 * Bn * Hn * 2 / 16; i += NCTA * NTHREADS)
            z[i] = z4;
    }
    gbar(base + (++bar));

    // --- wavefront: phase w runs layers j with t = w - j --------------------
    const int slot = cta >> 6;             // 0..3: active-layer slot
    const int tile = cta & 63;             // 64 tiles of 128x64
    const int m0 = (tile >> 3) * 128;      // 8 m-tiles
    const int n0 = (tile & 7) * 64;        // 8 n-tiles

    for (int w = 0; w < Ln + 3; w++) {
        const int jhi = (w < 3) ? w : 3;
        const int jlo = (w > Ln - 1) ? (w - (Ln - 1)) : 0;
        const int nact = jhi - jlo + 1;
        if (slot < nact) {
            const int j = jhi - slot;
            const int t = w - j;
            const int pin = t & 1, pout = pin ^ 1;
            const __half* A1 = &g_S16[pin][j][0][0];
            const __half* A2 = (j > 0) ? &g_S16[pout][j - 1][0][0] : A1;
            const __half* W1 = &g_W16[j][0][0];
            const __half* W2 = (j > 0) ? &g_W16[4 + j - 1][0][0] : W1;
            const float* bias = bc + j * Hn;
            __half* Cout = &g_S16[pout][j][0][0];
            switch (j) {
                case 0:
                    do_job<false, true, false>(&sm, t, A1, A2, W1, W2, bias, x, Win0, Cout, m0, n0);
                    break;
                case 3:
                    do_job<true, false, true>(&sm, t, A1, A2, W1, W2, bias, x, Win0, Cout, m0, n0);
                    break;
                default:
                    do_job<true, false, false>(&sm, t, A1, A2, W1, W2, bias, x, Win0, Cout, m0, n0);
                    break;
            }
        }
        gbar(base + (++bar));
    }
}

// ---------------------------------------------------------------------------
// Log-prob partials: warp (b, tc) handles 8 timesteps, writes g_lp[tc][b].
// ---------------------------------------------------------------------------
__global__ void logp_part(const float* __restrict__ Wout,  // [H][2]
                          const float* __restrict__ bout,  // [2]
                          const int*   __restrict__ xsym)  // [B][L]
{
    const int gw   = (blockIdx.x * blockDim.x + threadIdx.x) >> 5;
    const int lane = threadIdx.x & 31;
    const int b  = gw >> 3;
    const int tc = gw & 7;
    if (b >= Bn) return;

    float w0[16], w1[16];
#pragma unroll
    for (int i = 0; i < 8; i++) {
        const int k = lane * 2 + 64 * i;
        w0[2 * i]     = Wout[k * 2 + 0];
        w1[2 * i]     = Wout[k * 2 + 1];
        w0[2 * i + 1] = Wout[(k + 1) * 2 + 0];
        w1[2 * i + 1] = Wout[(k + 1) * 2 + 1];
    }
    const float b0 = bout[0], b1 = bout[1];

    float acc = 0.f;
#pragma unroll
    for (int tt = 0; tt < 8; tt++) {
        const int t = tc * 8 + tt;
        const __half* h = &g_h16[t][b][0];
        float s0 = 0.f, s1 = 0.f;
#pragma unroll
        for (int i = 0; i < 8; i++) {
            const __half2 hv = *reinterpret_cast<const __half2*>(&h[lane * 2 + 64 * i]);
            const float h0 = __half2float(hv.x);
            const float h1 = __half2float(hv.y);
            s0 += h0 * w0[2 * i] + h1 * w0[2 * i + 1];
            s1 += h0 * w1[2 * i] + h1 * w1[2 * i + 1];
        }
#pragma unroll
        for (int off = 16; off > 0; off >>= 1) {
            s0 += __shfl_xor_sync(0xffffffffu, s0, off);
            s1 += __shfl_xor_sync(0xffffffffu, s1, off);
        }
        s0 += b0; s1 += b1;
        const float m   = fmaxf(s0, s1);
        const float lse = m + logf(expf(s0 - m) + expf(s1 - m));
        const float sel = (xsym[b * Ln + t] == 0) ? s0 : s1;
        acc += sel - lse;
    }
    if (lane == 0) g_lp[tc][b] = acc;
}

// Deterministic final sum: out[b] = 0.5 * sum_tc g_lp[tc][b]
__global__ void logp_sum(float* __restrict__ out) {
    const int b = blockIdx.x * blockDim.x + threadIdx.x;
    if (b >= Bn) return;
    float s = 0.f;
#pragma unroll
    for (int tc = 0; tc < 8; tc++) s += g_lp[tc][b];
    out[b] = 0.5f * s;
}

// ---------------------------------------------------------------------------
extern "C" void kernel_launch(void* const* d_in, const int* in_sizes, int n_in,
                              void* d_out, int out_size) {
    (void)in_sizes; (void)n_in; (void)out_size;
    const int*   x        = (const int*)  d_in[0];  // [B, L]
    const float* Win0     = (const float*)d_in[1];  // [2, H]
    const float* Win_rest = (const float*)d_in[2];  // [3, H, H]
    const float* Wc       = (const float*)d_in[3];  // [4, H, H]
    const float* bc       = (const float*)d_in[4];  // [4, H]
    const float* Wout     = (const float*)d_in[5];  // [H, 2]
    const float* bout     = (const float*)d_in[6];  // [2]
    float* out = (float*)d_out;                     // [B]

    rnn_persistent<<<NCTA, NTHREADS>>>(x, Win0, Win_rest, Wc, bc);
    logp_part<<<(Bn * 8) / 8, 256>>>(Wout, bout, x);   // 1024 blocks, 8 warps each
    logp_sum<<<Bn / 256, 256>>>(out);
}